// round 1
// baseline (speedup 1.0000x reference)
#include <cuda_runtime.h>

// GyroLoss forward, fully fused.
// Level-4: groups of 16 increments; Level-5: pairs of level-4 groups.
// One thread per pair (32 increments). Scalar output via double accumulators.

#define DT_F 0.01f
#define HUBER_F 0.005f
#define NPER4 2048   // T/16 groups per batch at level 4
#define NPER5 1024   // per batch at level 5
#define N0 5

__device__ double g_sum4;
__device__ double g_sum5;

__device__ __forceinline__ void so3_exp9(float x, float y, float z, float R[9]) {
    float sq = x * x + y * y + z * z;
    float s, c;
    if (sq < 1e-12f) {
        s = 1.0f - sq * (1.0f / 6.0f);
        c = 0.5f - sq * (1.0f / 24.0f);
    } else {
        float a = sqrtf(fmaxf(sq, 1e-16f));
        float sa, ca;
        sincosf(a, &sa, &ca);
        s = sa / a;
        c = (1.0f - ca) / (a * a);
    }
    float xx = x * x, yy = y * y, zz = z * z;
    float xy = x * y, xz = x * z, yz = y * z;
    R[0] = 1.0f - c * (yy + zz);
    R[1] = c * xy - s * z;
    R[2] = c * xz + s * y;
    R[3] = c * xy + s * z;
    R[4] = 1.0f - c * (xx + zz);
    R[5] = c * yz - s * x;
    R[6] = c * xz - s * y;
    R[7] = c * yz + s * x;
    R[8] = 1.0f - c * (xx + yy);
}

__device__ __forceinline__ void mm3(const float A[9], const float B[9], float C[9]) {
#pragma unroll
    for (int i = 0; i < 3; i++) {
#pragma unroll
        for (int j = 0; j < 3; j++) {
            C[3 * i + j] = A[3 * i + 0] * B[0 + j]
                         + A[3 * i + 1] * B[3 + j]
                         + A[3 * i + 2] * B[6 + j];
        }
    }
}

// sum of Huber losses of so3_log(A^T B) / HUBER over 3 components
__device__ __forceinline__ float huber3_bmtm_log(const float A[9], const float B[9]) {
    // M[i][j] = sum_k A[k][i]*B[k][j]
    float m00 = A[0]*B[0] + A[3]*B[3] + A[6]*B[6];
    float m11 = A[1]*B[1] + A[4]*B[4] + A[7]*B[7];
    float m22 = A[2]*B[2] + A[5]*B[5] + A[8]*B[8];
    float m21 = A[2]*B[1] + A[5]*B[4] + A[8]*B[7];
    float m12 = A[1]*B[2] + A[4]*B[5] + A[7]*B[8];
    float m02 = A[0]*B[2] + A[3]*B[5] + A[6]*B[8];
    float m20 = A[2]*B[0] + A[5]*B[3] + A[8]*B[6];
    float m10 = A[1]*B[0] + A[4]*B[3] + A[7]*B[6];
    float m01 = A[0]*B[1] + A[3]*B[4] + A[6]*B[7];
    float tr  = m00 + m11 + m22;
    float cs  = fminf(fmaxf(0.5f * (tr - 1.0f), -1.0f + 1e-7f), 1.0f - 1e-7f);
    float ang = acosf(cs);
    float sfac = ang / (2.0f * sinf(ang));
    float v[3];
    v[0] = sfac * (m21 - m12);
    v[1] = sfac * (m02 - m20);
    v[2] = sfac * (m10 - m01);
    float acc = 0.0f;
#pragma unroll
    for (int t = 0; t < 3; t++) {
        float z = v[t] * (1.0f / HUBER_F);
        float az = fabsf(z);
        acc += (az < 1.0f) ? (0.5f * z * z) : (az - 0.5f);
    }
    return acc;
}

// Compose 16 increments: O = exp(dt*w0) * exp(dt*w1) * ... * exp(dt*w15)
// p points at 12 float4 (48 floats = 16 x vec3), 16B-aligned.
__device__ __forceinline__ void compute_om16(const float4* __restrict__ p, float O[9]) {
#pragma unroll
    for (int c = 0; c < 4; c++) {
        float4 q0 = p[3 * c + 0];
        float4 q1 = p[3 * c + 1];
        float4 q2 = p[3 * c + 2];
        float v[12] = {q0.x, q0.y, q0.z, q0.w,
                       q1.x, q1.y, q1.z, q1.w,
                       q2.x, q2.y, q2.z, q2.w};
#pragma unroll
        for (int k = 0; k < 4; k++) {
            float R[9];
            so3_exp9(DT_F * v[3 * k], DT_F * v[3 * k + 1], DT_F * v[3 * k + 2], R);
            if (c == 0 && k == 0) {
#pragma unroll
                for (int t = 0; t < 9; t++) O[t] = R[t];
            } else {
                float T[9];
                mm3(O, R, T);
#pragma unroll
                for (int t = 0; t < 9; t++) O[t] = T[t];
            }
        }
    }
}

__global__ void gyro_init_kernel() {
    g_sum4 = 0.0;
    g_sum5 = 0.0;
}

__global__ void __launch_bounds__(128)
gyro_main_kernel(const float* __restrict__ xs, const float* __restrict__ hx) {
    int p = blockIdx.x * blockDim.x + threadIdx.x;   // pair index, grid sized exactly

    const float4* hp = reinterpret_cast<const float4*>(hx) + (size_t)p * 24;
    float Oa[9], Ob[9];
    compute_om16(hp, Oa);
    compute_om16(hp + 12, Ob);

    // ground-truth strided rotations (offset is 192B-aligned -> safe float4)
    const float4* xa = reinterpret_cast<const float4*>(xs + (size_t)(2 * p) * 48);
    const float4* xb = reinterpret_cast<const float4*>(xs + (size_t)(2 * p) * 48 + 48);
    float4 qa = *xa;
    float4 qb = *xb;
    float Ra[9], Rb[9];
    so3_exp9(qa.x, qa.y, qa.z, Ra);
    so3_exp9(qb.x, qb.y, qb.z, Rb);

    // level-4 residuals (drop first N0 per batch of NPER4)
    int i = (2 * p) & (NPER4 - 1);
    float s4 = 0.0f;
    if (i >= N0)     s4 += huber3_bmtm_log(Oa, Ra);
    if (i + 1 >= N0) s4 += huber3_bmtm_log(Ob, Rb);

    // level-5
    float O2[9], R2[9];
    mm3(Oa, Ob, O2);
    mm3(Ra, Rb, R2);
    int j = p & (NPER5 - 1);
    float s5 = (j >= N0) ? huber3_bmtm_log(O2, R2) : 0.0f;

    // warp reduce
#pragma unroll
    for (int off = 16; off > 0; off >>= 1) {
        s4 += __shfl_down_sync(0xFFFFFFFFu, s4, off);
        s5 += __shfl_down_sync(0xFFFFFFFFu, s5, off);
    }
    __shared__ float sh4[4];
    __shared__ float sh5[4];
    int lane = threadIdx.x & 31;
    int warp = threadIdx.x >> 5;
    if (lane == 0) { sh4[warp] = s4; sh5[warp] = s5; }
    __syncthreads();
    if (threadIdx.x == 0) {
        float b4 = sh4[0] + sh4[1] + sh4[2] + sh4[3];
        float b5 = sh5[0] + sh5[1] + sh5[2] + sh5[3];
        atomicAdd(&g_sum4, (double)b4);
        atomicAdd(&g_sum5, (double)b5);
    }
}

__global__ void gyro_fin_kernel(float* __restrict__ out, int cnt4, int cnt5) {
    // loss = W*HUBER^2 * (mean4 + 0.5*mean5), W*HUBER^2 = 1e6 * 0.005^2 = 25
    double loss = 25.0 * (g_sum4 / (double)cnt4 + 0.5 * g_sum5 / (double)cnt5);
    out[0] = (float)loss;
}

extern "C" void kernel_launch(void* const* d_in, const int* in_sizes, int n_in,
                              void* d_out, int out_size) {
    const float* xs = (const float*)d_in[0];
    // d_in[1] = dp, unused by forward
    const float* hx = (const float*)d_in[2];

    int total = in_sizes[2];          // N*T*3 = 6291456
    int pairs = total / 96;           // 65536 pairs of 16-groups
    int nbatch = 64;                  // N
    int g4_per_batch = (total / (3 * 16)) / nbatch;   // 2048
    int g5_per_batch = g4_per_batch / 2;               // 1024
    int cnt4 = nbatch * (g4_per_batch - N0) * 3;       // 392256
    int cnt5 = nbatch * (g5_per_batch - N0) * 3;       // 195648

    gyro_init_kernel<<<1, 1>>>();
    gyro_main_kernel<<<pairs / 128, 128>>>(xs, hx);
    gyro_fin_kernel<<<1, 1>>>((float*)d_out, cnt4, cnt5);
}

// round 2
// speedup vs baseline: 1.2243x; 1.2243x over previous
#include <cuda_runtime.h>

// GyroLoss forward, single fused kernel.
// Level-4: groups of 16 increments; Level-5: pairs of level-4 groups.
// One thread per pair (32 increments). Last-block finalize writes scalar out.

#define DT_F 0.01f
#define HUBER_F 0.005f
#define NPER4 2048   // T/16 groups per batch at level 4
#define NPER5 1024   // per batch at level 5
#define N0 5

__device__ double g_sum4 = 0.0;
__device__ double g_sum5 = 0.0;
__device__ unsigned int g_count = 0u;

// Full-accuracy exp (used only for xs, 2 per thread; angle can be O(1..6))
__device__ __forceinline__ void so3_exp9_full(float x, float y, float z, float R[9]) {
    float sq = x * x + y * y + z * z;
    float s, c;
    if (sq < 1e-12f) {
        s = 1.0f - sq * (1.0f / 6.0f);
        c = 0.5f - sq * (1.0f / 24.0f);
    } else {
        float a = sqrtf(fmaxf(sq, 1e-16f));
        float sa, ca;
        sincosf(a, &sa, &ca);
        s = sa / a;
        c = (1.0f - ca) / (a * a);
    }
    float xx = x * x, yy = y * y, zz = z * z;
    float xy = x * y, xz = x * z, yz = y * z;
    R[0] = 1.0f - c * (yy + zz);
    R[1] = c * xy - s * z;
    R[2] = c * xz + s * y;
    R[3] = c * xy + s * z;
    R[4] = 1.0f - c * (xx + zz);
    R[5] = c * yz - s * x;
    R[6] = c * xz - s * y;
    R[7] = c * yz + s * x;
    R[8] = 1.0f - c * (xx + yy);
}

// Small-angle exp: |phi| = dt*|w| <= ~0.1, sq <= ~1e-2.
// Taylor: sin(a)/a = 1 - sq/6 + sq^2/120, (1-cos a)/a^2 = 1/2 - sq/24 + sq^2/720.
// Error ~ sq^3/5040 < 2e-10 -> far below tolerance.
__device__ __forceinline__ void so3_exp9_small(float x, float y, float z, float R[9]) {
    float sq = x * x + y * y + z * z;
    float s = 1.0f + sq * (-(1.0f / 6.0f) + sq * (1.0f / 120.0f));
    float c = 0.5f + sq * (-(1.0f / 24.0f) + sq * (1.0f / 720.0f));
    float xx = x * x, yy = y * y, zz = z * z;
    float xy = x * y, xz = x * z, yz = y * z;
    R[0] = 1.0f - c * (yy + zz);
    R[1] = c * xy - s * z;
    R[2] = c * xz + s * y;
    R[3] = c * xy + s * z;
    R[4] = 1.0f - c * (xx + zz);
    R[5] = c * yz - s * x;
    R[6] = c * xz - s * y;
    R[7] = c * yz + s * x;
    R[8] = 1.0f - c * (xx + yy);
}

__device__ __forceinline__ void mm3(const float A[9], const float B[9], float C[9]) {
#pragma unroll
    for (int i = 0; i < 3; i++) {
#pragma unroll
        for (int j = 0; j < 3; j++) {
            C[3 * i + j] = fmaf(A[3 * i + 0], B[0 + j],
                           fmaf(A[3 * i + 1], B[3 + j],
                                A[3 * i + 2] * B[6 + j]));
        }
    }
}

// sum of Huber losses of so3_log(A^T B) / HUBER over 3 components
__device__ __forceinline__ float huber3_bmtm_log(const float A[9], const float B[9]) {
    // M[i][j] = sum_k A[k][i]*B[k][j]
    float m00 = A[0]*B[0] + A[3]*B[3] + A[6]*B[6];
    float m11 = A[1]*B[1] + A[4]*B[4] + A[7]*B[7];
    float m22 = A[2]*B[2] + A[5]*B[5] + A[8]*B[8];
    float m21 = A[2]*B[1] + A[5]*B[4] + A[8]*B[7];
    float m12 = A[1]*B[2] + A[4]*B[5] + A[7]*B[8];
    float m02 = A[0]*B[2] + A[3]*B[5] + A[6]*B[8];
    float m20 = A[2]*B[0] + A[5]*B[3] + A[8]*B[6];
    float m10 = A[1]*B[0] + A[4]*B[3] + A[7]*B[6];
    float m01 = A[0]*B[1] + A[3]*B[4] + A[6]*B[7];
    float tr  = m00 + m11 + m22;
    float cs  = fminf(fmaxf(0.5f * (tr - 1.0f), -1.0f + 1e-7f), 1.0f - 1e-7f);
    float ang = acosf(cs);
    float sfac = ang / (2.0f * sinf(ang));
    float v0 = sfac * (m21 - m12);
    float v1 = sfac * (m02 - m20);
    float v2 = sfac * (m10 - m01);
    float acc = 0.0f;
#pragma unroll
    for (int t = 0; t < 3; t++) {
        float z = ((t == 0) ? v0 : (t == 1) ? v1 : v2) * (1.0f / HUBER_F);
        float az = fabsf(z);
        acc += (az < 1.0f) ? (0.5f * z * z) : (az - 0.5f);
    }
    return acc;
}

// Compose 16 increments: O = exp(dt*w0) * ... * exp(dt*w15)
// p points at 12 float4 (48 floats = 16 x vec3), 16B-aligned.
__device__ __forceinline__ void compute_om16(const float4* __restrict__ p, float O[9]) {
#pragma unroll
    for (int c = 0; c < 4; c++) {
        float4 q0 = p[3 * c + 0];
        float4 q1 = p[3 * c + 1];
        float4 q2 = p[3 * c + 2];
        float v[12] = {q0.x, q0.y, q0.z, q0.w,
                       q1.x, q1.y, q1.z, q1.w,
                       q2.x, q2.y, q2.z, q2.w};
#pragma unroll
        for (int k = 0; k < 4; k++) {
            float R[9];
            so3_exp9_small(DT_F * v[3 * k], DT_F * v[3 * k + 1], DT_F * v[3 * k + 2], R);
            if (c == 0 && k == 0) {
#pragma unroll
                for (int t = 0; t < 9; t++) O[t] = R[t];
            } else {
                float T[9];
                mm3(O, R, T);
#pragma unroll
                for (int t = 0; t < 9; t++) O[t] = T[t];
            }
        }
    }
}

#define TPB 256

__global__ void __launch_bounds__(TPB)
gyro_main_kernel(const float* __restrict__ xs, const float* __restrict__ hx,
                 float* __restrict__ out, int cnt4, int cnt5) {
    int p = blockIdx.x * blockDim.x + threadIdx.x;   // pair index, grid sized exactly

    const float4* hp = reinterpret_cast<const float4*>(hx) + (size_t)p * 24;
    float Oa[9], Ob[9];
    compute_om16(hp, Oa);
    compute_om16(hp + 12, Ob);

    // ground-truth strided rotations (offset is 192B-aligned -> safe float4)
    const float4* xa = reinterpret_cast<const float4*>(xs + (size_t)(2 * p) * 48);
    const float4* xb = reinterpret_cast<const float4*>(xs + (size_t)(2 * p) * 48 + 48);
    float4 qa = *xa;
    float4 qb = *xb;
    float Ra[9], Rb[9];
    so3_exp9_full(qa.x, qa.y, qa.z, Ra);
    so3_exp9_full(qb.x, qb.y, qb.z, Rb);

    // level-4 residuals (drop first N0 per batch of NPER4)
    int i = (2 * p) & (NPER4 - 1);
    float s4 = 0.0f;
    if (i >= N0)     s4 += huber3_bmtm_log(Oa, Ra);
    if (i + 1 >= N0) s4 += huber3_bmtm_log(Ob, Rb);

    // level-5
    float O2[9], R2[9];
    mm3(Oa, Ob, O2);
    mm3(Ra, Rb, R2);
    int j = p & (NPER5 - 1);
    float s5 = (j >= N0) ? huber3_bmtm_log(O2, R2) : 0.0f;

    // warp reduce
#pragma unroll
    for (int off = 16; off > 0; off >>= 1) {
        s4 += __shfl_down_sync(0xFFFFFFFFu, s4, off);
        s5 += __shfl_down_sync(0xFFFFFFFFu, s5, off);
    }
    __shared__ float sh4[TPB / 32];
    __shared__ float sh5[TPB / 32];
    int lane = threadIdx.x & 31;
    int warp = threadIdx.x >> 5;
    if (lane == 0) { sh4[warp] = s4; sh5[warp] = s5; }
    __syncthreads();

    if (threadIdx.x == 0) {
        float b4 = 0.0f, b5 = 0.0f;
#pragma unroll
        for (int w = 0; w < TPB / 32; w++) { b4 += sh4[w]; b5 += sh5[w]; }
        atomicAdd(&g_sum4, (double)b4);
        atomicAdd(&g_sum5, (double)b5);
        __threadfence();
        unsigned int ticket = atomicAdd(&g_count, 1u);
        if (ticket == gridDim.x - 1) {
            // last block: all prior atomics visible (fence + atomic ordering)
            double s4t = atomicAdd(&g_sum4, 0.0);
            double s5t = atomicAdd(&g_sum5, 0.0);
            // loss = W*HUBER^2 * (mean4 + 0.5*mean5); W*HUBER^2 = 1e6 * 0.005^2 = 25
            double loss = 25.0 * (s4t / (double)cnt4 + 0.5 * s5t / (double)cnt5);
            out[0] = (float)loss;
            // reset for next (graph-replayed) call — same stream, so safe
            g_sum4 = 0.0;
            g_sum5 = 0.0;
            __threadfence();
            g_count = 0u;
        }
    }
}

extern "C" void kernel_launch(void* const* d_in, const int* in_sizes, int n_in,
                              void* d_out, int out_size) {
    const float* xs = (const float*)d_in[0];
    // d_in[1] = dp, unused by forward
    const float* hx = (const float*)d_in[2];

    int total = in_sizes[2];          // N*T*3 = 6291456
    int pairs = total / 96;           // 65536 pairs of 16-groups
    int nbatch = 64;                  // N
    int g4_per_batch = (total / (3 * 16)) / nbatch;   // 2048
    int g5_per_batch = g4_per_batch / 2;               // 1024
    int cnt4 = nbatch * (g4_per_batch - N0) * 3;       // 392256
    int cnt5 = nbatch * (g5_per_batch - N0) * 3;       // 195648

    gyro_main_kernel<<<pairs / TPB, TPB>>>(xs, hx, (float*)d_out, cnt4, cnt5);
}

// round 3
// speedup vs baseline: 1.3877x; 1.1335x over previous
#include <cuda_runtime.h>

// GyroLoss forward, single fused kernel.
// One thread per 16-increment group (131072 threads). Level-5 combine across
// lane pairs via shuffles. Last-block finalize writes the scalar output.

#define DT_F 0.01f
#define HUBER_F 0.005f
#define NPER4 2048   // groups per batch at level 4
#define NPER5 1024   // pairs per batch at level 5
#define N0 5
#define TPB 256

__device__ double g_sum4 = 0.0;
__device__ double g_sum5 = 0.0;
__device__ unsigned int g_count = 0u;

// Full-accuracy exp (used only for xs; angle can be O(1..6))
__device__ __forceinline__ void so3_exp9_full(float x, float y, float z, float R[9]) {
    float sq = x * x + y * y + z * z;
    float s, c;
    if (sq < 1e-12f) {
        s = 1.0f - sq * (1.0f / 6.0f);
        c = 0.5f - sq * (1.0f / 24.0f);
    } else {
        float a = sqrtf(fmaxf(sq, 1e-16f));
        float sa, ca;
        sincosf(a, &sa, &ca);
        s = sa / a;
        c = (1.0f - ca) / (a * a);
    }
    float xx = x * x, yy = y * y, zz = z * z;
    float xy = x * y, xz = x * z, yz = y * z;
    R[0] = 1.0f - c * (yy + zz);
    R[1] = c * xy - s * z;
    R[2] = c * xz + s * y;
    R[3] = c * xy + s * z;
    R[4] = 1.0f - c * (xx + zz);
    R[5] = c * yz - s * x;
    R[6] = c * xz - s * y;
    R[7] = c * yz + s * x;
    R[8] = 1.0f - c * (xx + yy);
}

// Small-angle exp: |phi| = dt*|w|, sq <= ~1e-2. Taylor error < 2e-10.
__device__ __forceinline__ void so3_exp9_small(float x, float y, float z, float R[9]) {
    float sq = x * x + y * y + z * z;
    float s = 1.0f + sq * (-(1.0f / 6.0f) + sq * (1.0f / 120.0f));
    float c = 0.5f + sq * (-(1.0f / 24.0f) + sq * (1.0f / 720.0f));
    float xx = x * x, yy = y * y, zz = z * z;
    float xy = x * y, xz = x * z, yz = y * z;
    R[0] = 1.0f - c * (yy + zz);
    R[1] = c * xy - s * z;
    R[2] = c * xz + s * y;
    R[3] = c * xy + s * z;
    R[4] = 1.0f - c * (xx + zz);
    R[5] = c * yz - s * x;
    R[6] = c * xz - s * y;
    R[7] = c * yz + s * x;
    R[8] = 1.0f - c * (xx + yy);
}

__device__ __forceinline__ void mm3(const float A[9], const float B[9], float C[9]) {
#pragma unroll
    for (int i = 0; i < 3; i++) {
#pragma unroll
        for (int j = 0; j < 3; j++) {
            C[3 * i + j] = fmaf(A[3 * i + 0], B[0 + j],
                           fmaf(A[3 * i + 1], B[3 + j],
                                A[3 * i + 2] * B[6 + j]));
        }
    }
}

// sum of Huber losses of so3_log(A^T B) / HUBER over 3 components
__device__ __forceinline__ float huber3_bmtm_log(const float A[9], const float B[9]) {
    float m00 = A[0]*B[0] + A[3]*B[3] + A[6]*B[6];
    float m11 = A[1]*B[1] + A[4]*B[4] + A[7]*B[7];
    float m22 = A[2]*B[2] + A[5]*B[5] + A[8]*B[8];
    float m21 = A[2]*B[1] + A[5]*B[4] + A[8]*B[7];
    float m12 = A[1]*B[2] + A[4]*B[5] + A[7]*B[8];
    float m02 = A[0]*B[2] + A[3]*B[5] + A[6]*B[8];
    float m20 = A[2]*B[0] + A[5]*B[3] + A[8]*B[6];
    float m10 = A[1]*B[0] + A[4]*B[3] + A[7]*B[6];
    float m01 = A[0]*B[1] + A[3]*B[4] + A[6]*B[7];
    float tr  = m00 + m11 + m22;
    float cs  = fminf(fmaxf(0.5f * (tr - 1.0f), -1.0f + 1e-7f), 1.0f - 1e-7f);
    float ang = acosf(cs);
    float sfac = ang / (2.0f * sinf(ang));
    float v0 = sfac * (m21 - m12);
    float v1 = sfac * (m02 - m20);
    float v2 = sfac * (m10 - m01);
    float acc = 0.0f;
#pragma unroll
    for (int t = 0; t < 3; t++) {
        float z = ((t == 0) ? v0 : (t == 1) ? v1 : v2) * (1.0f / HUBER_F);
        float az = fabsf(z);
        acc += (az < 1.0f) ? (0.5f * z * z) : (az - 0.5f);
    }
    return acc;
}

__global__ void __launch_bounds__(TPB)
gyro_main_kernel(const float* __restrict__ xs, const float* __restrict__ hx,
                 float* __restrict__ out, int cnt4, int cnt5) {
    int g = blockIdx.x * blockDim.x + threadIdx.x;   // group index (16 increments)

    // --- compose 16 predicted increments into O ---
    const float4* hp = reinterpret_cast<const float4*>(hx) + (size_t)g * 12;
    float O[9];
    {
        bool first = true;
#pragma unroll
        for (int c = 0; c < 4; c++) {
            float4 q0 = hp[3 * c + 0];
            float4 q1 = hp[3 * c + 1];
            float4 q2 = hp[3 * c + 2];
            float v[12] = {q0.x, q0.y, q0.z, q0.w,
                           q1.x, q1.y, q1.z, q1.w,
                           q2.x, q2.y, q2.z, q2.w};
#pragma unroll
            for (int k = 0; k < 4; k++) {
                float R[9];
                so3_exp9_small(DT_F * v[3 * k], DT_F * v[3 * k + 1], DT_F * v[3 * k + 2], R);
                if (first) {
#pragma unroll
                    for (int t = 0; t < 9; t++) O[t] = R[t];
                    first = false;
                } else {
                    float T[9];
                    mm3(O, R, T);
#pragma unroll
                    for (int t = 0; t < 9; t++) O[t] = T[t];
                }
            }
        }
    }

    // --- ground-truth rotation for this group (48-float = 192B aligned) ---
    float4 qa = *reinterpret_cast<const float4*>(xs + (size_t)g * 48);
    float R[9];
    so3_exp9_full(qa.x, qa.y, qa.z, R);

    // --- level-4 residual ---
    int i4 = g & (NPER4 - 1);
    float s4 = (i4 >= N0) ? huber3_bmtm_log(O, R) : 0.0f;

    // --- level-5: even lane of each pair pulls partner's O,R and combines ---
    float Op[9], Rp[9];
#pragma unroll
    for (int t = 0; t < 9; t++) {
        Op[t] = __shfl_down_sync(0xFFFFFFFFu, O[t], 1);
        Rp[t] = __shfl_down_sync(0xFFFFFFFFu, R[t], 1);
    }
    float s5 = 0.0f;
    if ((g & 1) == 0) {
        int j5 = (g >> 1) & (NPER5 - 1);
        if (j5 >= N0) {
            float O2[9], R2[9];
            mm3(O, Op, O2);
            mm3(R, Rp, R2);
            s5 = huber3_bmtm_log(O2, R2);
        }
    }

    // --- reduction ---
#pragma unroll
    for (int off = 16; off > 0; off >>= 1) {
        s4 += __shfl_down_sync(0xFFFFFFFFu, s4, off);
        s5 += __shfl_down_sync(0xFFFFFFFFu, s5, off);
    }
    __shared__ float sh4[TPB / 32];
    __shared__ float sh5[TPB / 32];
    int lane = threadIdx.x & 31;
    int warp = threadIdx.x >> 5;
    if (lane == 0) { sh4[warp] = s4; sh5[warp] = s5; }
    __syncthreads();

    if (threadIdx.x == 0) {
        float b4 = 0.0f, b5 = 0.0f;
#pragma unroll
        for (int w = 0; w < TPB / 32; w++) { b4 += sh4[w]; b5 += sh5[w]; }
        atomicAdd(&g_sum4, (double)b4);
        atomicAdd(&g_sum5, (double)b5);
        __threadfence();
        unsigned int ticket = atomicAdd(&g_count, 1u);
        if (ticket == gridDim.x - 1) {
            double s4t = atomicAdd(&g_sum4, 0.0);
            double s5t = atomicAdd(&g_sum5, 0.0);
            // loss = W*HUBER^2 * (mean4 + 0.5*mean5); W*HUBER^2 = 25
            double loss = 25.0 * (s4t / (double)cnt4 + 0.5 * s5t / (double)cnt5);
            out[0] = (float)loss;
            g_sum4 = 0.0;
            g_sum5 = 0.0;
            __threadfence();
            g_count = 0u;
        }
    }
}

extern "C" void kernel_launch(void* const* d_in, const int* in_sizes, int n_in,
                              void* d_out, int out_size) {
    const float* xs = (const float*)d_in[0];
    // d_in[1] = dp, unused by forward
    const float* hx = (const float*)d_in[2];

    int total = in_sizes[2];            // N*T*3 = 6291456
    int groups = total / 48;            // 131072 groups of 16
    int nbatch = 64;                    // N
    int g4_per_batch = groups / nbatch; // 2048
    int g5_per_batch = g4_per_batch / 2;
    int cnt4 = nbatch * (g4_per_batch - N0) * 3;   // 392256
    int cnt5 = nbatch * (g5_per_batch - N0) * 3;   // 195648

    gyro_main_kernel<<<groups / TPB, TPB>>>(xs, hx, (float*)d_out, cnt4, cnt5);
}